// round 14
// baseline (speedup 1.0000x reference)
#include <cuda_runtime.h>
#include <math.h>

#define NN 100000
#define NE 3200000
#define NR 15
#define FIN 35
#define OD 32
#define FLIP_MASK 5
#define GA 1024
#define SB 512

__device__ float g_X0[NN*FIN];
__device__ float g_Xc[NN*OD];
__device__ float g_h[NN*OD];
__device__ float g_xr[(size_t)NR*NN*OD];
__device__ float g_qd[NR*NN];
__device__ float g_kd[NR*NN];
__device__ float g_alpha[NE];
__device__ int   g_srcS[NE];
__device__ int   g_etS[NE];
__device__ int   g_hist[NN];
__device__ int   g_inc[NN];
__device__ int   g_rowptr[NN+1];
__device__ int   g_cursor[NN];
__device__ int   g_btot[128];
__device__ int   g_boff[128];
__device__ double g_pp[SB*9];
__device__ double g_fp[SB*2];
__device__ double g_hp[GA*2];
__device__ double g_pool[OD];
__device__ unsigned g_maxbits;
__device__ double g_mu[3];
__device__ double g_cov[6];
__device__ float g_M[9];
__device__ float g_fmean, g_fstd;
__device__ float g_hmu, g_hsig;

// ---------- pos stats ----------
__global__ void kpos_partials(const float* __restrict__ d){
  double a[9];
#pragma unroll
  for(int i=0;i<9;i++) a[i]=0.0;
  for(int n=blockIdx.x*blockDim.x+threadIdx.x;n<NN;n+=gridDim.x*blockDim.x){
    double x=d[n*FIN],y=d[n*FIN+1],z=d[n*FIN+2];
    a[0]+=x;a[1]+=y;a[2]+=z;a[3]+=x*x;a[4]+=x*y;a[5]+=x*z;a[6]+=y*y;a[7]+=y*z;a[8]+=z*z;
  }
  __shared__ double sm[256];
  for(int c=0;c<9;c++){
    sm[threadIdx.x]=a[c];__syncthreads();
    for(int o=128;o;o>>=1){ if(threadIdx.x<(unsigned)o) sm[threadIdx.x]+=sm[threadIdx.x+o]; __syncthreads(); }
    if(!threadIdx.x) g_pp[blockIdx.x*9+c]=sm[0];
    __syncthreads();
  }
}

__global__ void kpos_final(){
  __shared__ double sm[512];
  __shared__ double tot[9];
  int t=threadIdx.x;
  for(int c=0;c<9;c++){
    sm[t]=g_pp[t*9+c];__syncthreads();
    for(int o=256;o;o>>=1){ if(t<o) sm[t]+=sm[t+o]; __syncthreads(); }
    if(!t) tot[c]=sm[0];
    __syncthreads();
  }
  if(t<OD) g_pool[t]=0.0;
  if(!t){
    double Nn=(double)NN;
    double mx=tot[0]/Nn,my=tot[1]/Nn,mz=tot[2]/Nn;
    g_mu[0]=mx;g_mu[1]=my;g_mu[2]=mz;
    g_cov[0]=tot[3]-Nn*mx*mx; g_cov[1]=tot[4]-Nn*mx*my; g_cov[2]=tot[5]-Nn*mx*mz;
    g_cov[3]=tot[6]-Nn*my*my; g_cov[4]=tot[7]-Nn*my*mz; g_cov[5]=tot[8]-Nn*mz*mz;
    g_maxbits=0u;
  }
}

__global__ void kmaxabs(const float* __restrict__ d){
  float m=0.f;
  float m0=(float)g_mu[0],m1=(float)g_mu[1],m2=(float)g_mu[2];
  for(int n=blockIdx.x*blockDim.x+threadIdx.x;n<NN;n+=gridDim.x*blockDim.x){
    m=fmaxf(m,fabsf(d[n*FIN]-m0));
    m=fmaxf(m,fabsf(d[n*FIN+1]-m1));
    m=fmaxf(m,fabsf(d[n*FIN+2]-m2));
  }
  __shared__ float sm[256];
  sm[threadIdx.x]=m;__syncthreads();
  for(int o=128;o;o>>=1){ if(threadIdx.x<(unsigned)o) sm[threadIdx.x]=fmaxf(sm[threadIdx.x],sm[threadIdx.x+o]); __syncthreads(); }
  if(!threadIdx.x) atomicMax(&g_maxbits,__float_as_uint(sm[0]));
}

// ---------- analytic 3x3 symmetric eigh (ascending) ----------
__global__ void keig(){
  double a00=g_cov[0],a01=g_cov[1],a02=g_cov[2],a11=g_cov[3],a12=g_cov[4],a22=g_cov[5];
  double V[3][3], lam[3];
  double p1=a01*a01+a02*a02+a12*a12;
  if(p1==0.0){
    double dd[3]={a00,a11,a22}; int idx[3]={0,1,2};
    for(int i=0;i<2;i++)for(int j=0;j<2-i;j++)
      if(dd[j]>dd[j+1]){double tt=dd[j];dd[j]=dd[j+1];dd[j+1]=tt;int ti=idx[j];idx[j]=idx[j+1];idx[j+1]=ti;}
    for(int k=0;k<3;k++){lam[k]=dd[k];for(int j=0;j<3;j++)V[j][k]=(j==idx[k])?1.0:0.0;}
  }else{
    double q=(a00+a11+a22)/3.0;
    double b00=a00-q,b11=a11-q,b22=a22-q;
    double p2=b00*b00+b11*b11+b22*b22+2.0*p1;
    double p=sqrt(p2/6.0);
    double c00=b00/p,c01=a01/p,c02=a02/p,c11=b11/p,c12=a12/p,c22=b22/p;
    double detB=c00*(c11*c22-c12*c12)-c01*(c01*c22-c12*c02)+c02*(c01*c12-c11*c02);
    double r=detB*0.5; r=r<-1.0?-1.0:(r>1.0?1.0:r);
    double phi=acos(r)/3.0;
    const double tp3=2.0943951023931953;
    lam[2]=q+2.0*p*cos(phi);
    lam[0]=q+2.0*p*cos(phi+tp3);
    lam[1]=3.0*q-lam[0]-lam[2];
    for(int kk=0;kk<2;kk++){
      int k=(kk==0)?0:2;
      double l=lam[k];
      double r0x=a00-l,r0y=a01,r0z=a02;
      double r1x=a01,r1y=a11-l,r1z=a12;
      double r2x=a02,r2y=a12,r2z=a22-l;
      double cx[3],cy[3],cz[3];
      cx[0]=r0y*r1z-r0z*r1y; cy[0]=r0z*r1x-r0x*r1z; cz[0]=r0x*r1y-r0y*r1x;
      cx[1]=r0y*r2z-r0z*r2y; cy[1]=r0z*r2x-r0x*r2z; cz[1]=r0x*r2y-r0y*r2x;
      cx[2]=r1y*r2z-r1z*r2y; cy[2]=r1z*r2x-r1x*r2z; cz[2]=r1x*r2y-r1y*r2x;
      int best=0; double bn=-1.0;
      for(int i=0;i<3;i++){double nn=cx[i]*cx[i]+cy[i]*cy[i]+cz[i]*cz[i];if(nn>bn){bn=nn;best=i;}}
      double innorm=1.0/sqrt(bn);
      V[0][k]=cx[best]*innorm;V[1][k]=cy[best]*innorm;V[2][k]=cz[best]*innorm;
    }
    double mx=V[1][2]*V[2][0]-V[2][2]*V[1][0];
    double my=V[2][2]*V[0][0]-V[0][2]*V[2][0];
    double mz=V[0][2]*V[1][0]-V[1][2]*V[0][0];
    double innm=1.0/sqrt(mx*mx+my*my+mz*mz);
    V[0][1]=mx*innm;V[1][1]=my*innm;V[2][1]=mz*innm;
  }
  for(int k=0;k<3;k++){
    int bj=0; double bv=fabs(V[0][k]);
    for(int j=1;j<3;j++){double av=fabs(V[j][k]);if(av>bv){bv=av;bj=j;}}
    double sgn=(V[bj][k]<0.0)?-1.0:1.0;
    if((FLIP_MASK>>k)&1) sgn=-sgn;
    V[0][k]*=sgn;V[1][k]*=sgn;V[2][k]*=sgn;
  }
  float mab=__uint_as_float(g_maxbits);
  float s=(1.0f/mab)*0.999999f;
  for(int j=0;j<3;j++)for(int k=0;k<3;k++) g_M[j*3+k]=(float)V[j][k]*s;
}

// ---------- feature LN stats ----------
__global__ void kfeat_partials(const float* __restrict__ d){
  double s=0.0,sq=0.0;
  for(int idx=blockIdx.x*blockDim.x+threadIdx.x;idx<NN*OD;idx+=gridDim.x*blockDim.x){
    int n=idx>>5,c=idx&31;
    double v=d[n*FIN+3+c];
    s+=v;sq+=v*v;
  }
  __shared__ double s1[256],s2[256];
  int t=threadIdx.x;
  s1[t]=s;s2[t]=sq;__syncthreads();
  for(int o=128;o;o>>=1){ if(t<o){s1[t]+=s1[t+o];s2[t]+=s2[t+o];} __syncthreads(); }
  if(!t){g_fp[blockIdx.x*2]=s1[0];g_fp[blockIdx.x*2+1]=s2[0];}
}

__global__ void kfeat_final(){
  __shared__ double s1[512],s2[512];
  int t=threadIdx.x;
  s1[t]=g_fp[t*2];s2[t]=g_fp[t*2+1];__syncthreads();
  for(int o=256;o;o>>=1){ if(t<o){s1[t]+=s1[t+o];s2[t]+=s2[t+o];} __syncthreads(); }
  if(!t){
    double M=(double)NN*OD;
    double mu=s1[0]/M;
    double var=s2[0]/M-mu*mu;
    g_fmean=(float)mu;
    g_fstd=(float)sqrt(var>0.0?var:0.0);
  }
}

// ---------- build layer-0 features ----------
__global__ void kbuildX(const float* __restrict__ d,const float* __restrict__ w,const float* __restrict__ b){
  int n=blockIdx.x*blockDim.x+threadIdx.x;
  if(n>=NN)return;
  float p0=d[n*FIN]-(float)g_mu[0];
  float p1=d[n*FIN+1]-(float)g_mu[1];
  float p2=d[n*FIN+2]-(float)g_mu[2];
#pragma unroll
  for(int k=0;k<3;k++)
    g_X0[n*FIN+k]=p0*g_M[k]+p1*g_M[3+k]+p2*g_M[6+k];
  float fm=g_fmean, inv=1.f/(g_fstd+1e-5f);
#pragma unroll
  for(int c=0;c<OD;c++)
    g_X0[n*FIN+3+c]=(d[n*FIN+3+c]-fm)*inv*w[c]+b[c];
}

// ---------- counting sort by dst ----------
__global__ void khz(){
  int i=blockIdx.x*blockDim.x+threadIdx.x;
  if(i<NN) g_hist[i]=0;
}
__global__ void khist(const int* __restrict__ dst){
  for(int e=blockIdx.x*blockDim.x+threadIdx.x;e<NE;e+=gridDim.x*blockDim.x)
    atomicAdd(&g_hist[dst[e]],1);
}
__global__ void kscanA(){
  __shared__ int s[1024];
  int t=threadIdx.x;
  int i=blockIdx.x*1024+t;
  s[t]=(i<NN)?g_hist[i]:0;
  __syncthreads();
  for(int o=1;o<1024;o<<=1){
    int tv=(t>=o)?s[t-o]:0;
    __syncthreads();
    s[t]+=tv;
    __syncthreads();
  }
  if(i<NN) g_inc[i]=s[t];
  if(t==1023) g_btot[blockIdx.x]=s[1023];
}
__global__ void kscanB(){
  int nb=(NN+1023)/1024, run=0;
  for(int b=0;b<nb;b++){g_boff[b]=run;run+=g_btot[b];}
  g_rowptr[NN]=run;
}
__global__ void kscanC(){
  int i=blockIdx.x*blockDim.x+threadIdx.x;
  if(i<NN){
    int rp=g_boff[i>>10]+g_inc[i]-g_hist[i];
    g_rowptr[i]=rp;
    g_cursor[i]=rp;
  }
}
__global__ void kscatter(const int* __restrict__ src,const int* __restrict__ dst,const int* __restrict__ et){
  for(int e=blockIdx.x*blockDim.x+threadIdx.x;e<NE;e+=gridDim.x*blockDim.x){
    int d=dst[e];
    int p=atomicAdd(&g_cursor[d],1);
    g_srcS[p]=src[e];
    g_etS[p]=et[e];
  }
}

// ---------- per-relation transform + q/k dots (4n x 4c register tile) ----------
__global__ void ktransform(int useX0,int Fin,const float* __restrict__ W,
                           const float* __restrict__ qv,const float* __restrict__ kv){
  __shared__ float sW[FIN*OD];   // [f][c]
  __shared__ float sX[64*FIN];   // [nl][f]
  int r=blockIdx.y, n0=blockIdx.x*64;
  int t=threadIdx.x;             // 128 threads
  const float* Wr=W+(size_t)r*Fin*OD;
  for(int i=t;i<Fin*OD;i+=128) sW[i]=Wr[i];
  const float* X=useX0?g_X0:g_Xc;
  for(int i=t;i<64*Fin;i+=128){
    int nl=i/Fin,f=i-nl*Fin;
    int n=n0+nl;
    sX[i]=(n<NN)?X[(size_t)n*Fin+f]:0.f;
  }
  __syncthreads();
  int tx=t&7, ty=t>>3;
  int c0=tx*4, nl0=ty*4;
  float acc[4][4];
#pragma unroll
  for(int i=0;i<4;i++)
#pragma unroll
    for(int j=0;j<4;j++) acc[i][j]=0.f;
  for(int f=0;f<Fin;f++){
    float4 wv=*(const float4*)&sW[f*OD+c0];
    float xv[4];
#pragma unroll
    for(int i=0;i<4;i++) xv[i]=sX[(nl0+i)*Fin+f];
#pragma unroll
    for(int i=0;i<4;i++){
      acc[i][0]+=xv[i]*wv.x; acc[i][1]+=xv[i]*wv.y;
      acc[i][2]+=xv[i]*wv.z; acc[i][3]+=xv[i]*wv.w;
    }
  }
  float q4[4],k4[4];
#pragma unroll
  for(int j=0;j<4;j++){ q4[j]=qv[c0+j]; k4[j]=kv[c0+j]; }
#pragma unroll
  for(int i=0;i<4;i++){
    int n=n0+nl0+i;
    bool ok=(n<NN);
    if(ok){
      float4 st; st.x=acc[i][0]; st.y=acc[i][1]; st.z=acc[i][2]; st.w=acc[i][3];
      *(float4*)&g_xr[((size_t)r*NN+n)*OD+c0]=st;
    }
    float qs_=acc[i][0]*q4[0]+acc[i][1]*q4[1]+acc[i][2]*q4[2]+acc[i][3]*q4[3];
    float ks_=acc[i][0]*k4[0]+acc[i][1]*k4[1]+acc[i][2]*k4[2]+acc[i][3]*k4[3];
    for(int o=1;o<8;o<<=1){
      qs_+=__shfl_xor_sync(0xffffffffu,qs_,o);
      ks_+=__shfl_xor_sync(0xffffffffu,ks_,o);
    }
    if(ok&&tx==0){ g_qd[r*NN+n]=qs_; g_kd[r*NN+n]=ks_; }
  }
}

// ---------- attention + aggregation: warp per destination node ----------
__global__ void kagg(const float* __restrict__ bias,int useprev){
  int lane=threadIdx.x&31;
  int warp=(blockIdx.x*blockDim.x+threadIdx.x)>>5;
  int nwarps=(gridDim.x*blockDim.x)>>5;
  float bv=bias[lane];
  float tsum=0.f,tsq=0.f;
  for(int n=warp;n<NN;n+=nwarps){
    int s0=g_rowptr[n], deg=g_rowptr[n+1]-s0;
    float hv;
    if(deg<=128){
      int addr_r[4]; float e_r[4];
      float m=-3.0e38f;
#pragma unroll
      for(int tt=0;tt<4;tt++){
        int i=lane+tt*32;
        e_r[tt]=-3.0e38f; addr_r[tt]=0;
        if(i<deg){
          int idx=s0+i;
          int et=g_etS[idx], sv=g_srcS[idx];
          addr_r[tt]=(et*NN+sv)*OD;
          float a=g_qd[et*NN+n]+g_kd[et*NN+sv];
          a=a>0.f?a:0.2f*a;
          e_r[tt]=a;
          m=fmaxf(m,a);
        }
      }
      for(int o=16;o;o>>=1) m=fmaxf(m,__shfl_xor_sync(0xffffffffu,m,o));
      float den=0.f;
#pragma unroll
      for(int tt=0;tt<4;tt++){
        int i=lane+tt*32;
        if(i<deg){ e_r[tt]=expf(e_r[tt]-m); den+=e_r[tt]; }
      }
      for(int o=16;o;o>>=1) den+=__shfl_xor_sync(0xffffffffu,den,o);
      float inv=1.f/(den+1e-16f);
      float acc=0.f;
#pragma unroll
      for(int tt=0;tt<4;tt++){
        int base=tt*32;
        if(base<deg){
          int cnt=deg-base; if(cnt>32) cnt=32;
          for(int l=0;l<cnt;l++){
            float e=__shfl_sync(0xffffffffu,e_r[tt],l);
            int ad=__shfl_sync(0xffffffffu,addr_r[tt],l);
            acc+=e*g_xr[ad+lane];
          }
        }
      }
      hv=acc*inv+bv;
    } else {
      float m=-3.0e38f;
      for(int i=lane;i<deg;i+=32){
        int idx=s0+i;
        int et=g_etS[idx], sv=g_srcS[idx];
        float a=g_qd[et*NN+n]+g_kd[et*NN+sv];
        a=a>0.f?a:0.2f*a;
        g_alpha[idx]=a;
        m=fmaxf(m,a);
      }
      for(int o=16;o;o>>=1) m=fmaxf(m,__shfl_xor_sync(0xffffffffu,m,o));
      float den=0.f;
      for(int i=lane;i<deg;i+=32){
        int idx=s0+i;
        float e=expf(g_alpha[idx]-m);
        g_alpha[idx]=e;
        den+=e;
      }
      for(int o=16;o;o>>=1) den+=__shfl_xor_sync(0xffffffffu,den,o);
      __syncwarp();
      float inv=1.f/(den+1e-16f);
      float acc=0.f;
      for(int j=0;j<deg;j++){
        int idx=s0+j;
        float e=g_alpha[idx];
        int et=g_etS[idx], sv=g_srcS[idx];
        acc+=e*g_xr[((size_t)et*NN+sv)*OD+lane];
      }
      hv=acc*inv+bv;
    }
    if(useprev) hv+=g_Xc[n*OD+lane];
    g_h[n*OD+lane]=hv;
    tsum+=hv; tsq+=hv*hv;
  }
  __shared__ double d1[256],d2[256];
  int t=threadIdx.x;
  d1[t]=(double)tsum; d2[t]=(double)tsq;
  __syncthreads();
  for(int o=128;o;o>>=1){ if(t<o){d1[t]+=d1[t+o];d2[t]+=d2[t+o];} __syncthreads(); }
  if(!t){g_hp[blockIdx.x*2]=d1[0];g_hp[blockIdx.x*2+1]=d2[0];}
}

__global__ void krstats(){
  __shared__ double sa[1024],sb[1024];
  int t=threadIdx.x;
  sa[t]=g_hp[t*2]; sb[t]=g_hp[t*2+1];
  __syncthreads();
  for(int o=512;o;o>>=1){ if(t<o){sa[t]+=sa[t+o];sb[t]+=sb[t+o];} __syncthreads(); }
  if(!t){
    double M=(double)NN*OD;
    double mu=sa[0]/M;
    double var=sb[0]/M-mu*mu;
    g_hmu=(float)mu;
    g_hsig=(float)sqrt(var>0?var:0);
  }
}

__global__ void knorm(const float* __restrict__ w,const float* __restrict__ b){
  int idx=blockIdx.x*blockDim.x+threadIdx.x;
  if(idx>=NN*OD)return;
  int c=idx&31;
  float v=(g_h[idx]-g_hmu)/(g_hsig+1e-5f)*w[c]+b[c];
  g_Xc[idx]=v/(1.f+expf(-v));
}

__global__ void kpoolp(){
  int lane=threadIdx.x&31;
  int warp=(blockIdx.x*blockDim.x+threadIdx.x)>>5;
  int nw=(gridDim.x*blockDim.x)>>5;
  double s=0.0;
  for(int n=warp;n<NN;n+=nw) s+=(double)g_Xc[n*OD+lane];
  atomicAdd(&g_pool[lane],s);
}

__global__ void kout(const float* __restrict__ Wl,const float* __restrict__ bl,float* __restrict__ out){
  int j=threadIdx.x;
  float s=bl[j];
  for(int c=0;c<OD;c++) s+=(float)(g_pool[c]/(double)NN)*Wl[j*OD+c];
  out[j]=s/(1.f+expf(-s));
}

extern "C" void kernel_launch(void* const* d_in,const int* in_sizes,int n_in,
                              void* d_out,int out_size){
  (void)in_sizes;(void)n_in;(void)out_size;
  const float* X1 =(const float*)d_in[0];
  const int*   ei =(const int*)  d_in[2];
  const int*   et =(const int*)  d_in[3];
  const float* W0 =(const float*)d_in[6];
  const float* q0 =(const float*)d_in[7];
  const float* k0 =(const float*)d_in[8];
  const float* b0 =(const float*)d_in[9];
  const float* Ws =(const float*)d_in[10];
  const float* qs =(const float*)d_in[11];
  const float* ks =(const float*)d_in[12];
  const float* bs =(const float*)d_in[13];
  const float* lnw=(const float*)d_in[14];
  const float* lnb=(const float*)d_in[15];
  const float* l1w=(const float*)d_in[16];
  const float* l1b_=(const float*)d_in[17];
  const float* lW =(const float*)d_in[18];
  const float* lb =(const float*)d_in[19];
  float* out=(float*)d_out;
  const int* src=ei;
  const int* dst=ei+NE;

  kpos_partials<<<SB,256>>>(X1);
  kpos_final<<<1,512>>>();
  kmaxabs<<<SB,256>>>(X1);
  keig<<<1,1>>>();
  kfeat_partials<<<SB,256>>>(X1);
  kfeat_final<<<1,512>>>();
  kbuildX<<<(NN+255)/256,256>>>(X1,l1w,l1b_);

  khz<<<(NN+255)/256,256>>>();
  khist<<<2048,256>>>(dst);
  kscanA<<<(NN+1023)/1024,1024>>>();
  kscanB<<<1,1>>>();
  kscanC<<<(NN+255)/256,256>>>();
  kscatter<<<2048,256>>>(src,dst,et);

  for(int i=0;i<4;i++){
    int useX0=(i==0);
    int Fin=useX0?FIN:OD;
    const float* W =useX0?W0:(Ws+(size_t)(i-1)*NR*OD*OD);
    const float* qv=useX0?q0:(qs+(i-1)*OD);
    const float* kv=useX0?k0:(ks+(i-1)*OD);
    const float* bv=useX0?b0:(bs+(i-1)*OD);
    ktransform<<<dim3((NN+63)/64,NR),128>>>(useX0,Fin,W,qv,kv);
    kagg<<<GA,256>>>(bv,i>0);
    krstats<<<1,1024>>>();
    knorm<<<(NN*OD+255)/256,256>>>(lnw+i*OD,lnb+i*OD);
  }

  kpoolp<<<512,256>>>();
  kout<<<1,256>>>(lW,lb,out);
}

// round 17
// speedup vs baseline: 1.1283x; 1.1283x over previous
#include <cuda_runtime.h>
#include <math.h>

#define NN 100000
#define NE 3200000
#define NR 15
#define FIN 35
#define OD 32
#define FLIP_MASK 5
#define GA 1024
#define SB 512

__device__ float g_X0[NN*FIN];
__device__ float g_Xc[NN*OD];
__device__ float g_h[NN*OD];
__device__ float g_xr[(size_t)NR*NN*OD];
__device__ float g_qd[NR*NN];
__device__ float g_kd[NR*NN];
__device__ float g_alpha[NE];
__device__ int   g_se[NE];          // packed: src | (etype<<17)
__device__ int   g_hist[NN];
__device__ int   g_inc[NN];
__device__ int   g_rowptr[NN+1];
__device__ int   g_cursor[NN];
__device__ int   g_btot[128];
__device__ int   g_boff[128];
__device__ double g_pp[SB*9];
__device__ double g_fp[SB*2];
__device__ double g_hp[GA*2];
__device__ double g_pool[OD];
__device__ unsigned g_maxbits;
__device__ double g_mu[3];
__device__ double g_cov[6];
__device__ float g_M[9];
__device__ float g_fmean, g_fstd;
__device__ float g_hmu, g_hsig;

__device__ __forceinline__ unsigned tf32cvt(float f){
  unsigned r; asm("cvt.rna.tf32.f32 %0,%1;" : "=r"(r) : "f"(f)); return r;
}

// ---------- pos stats ----------
__global__ void kpos_partials(const float* __restrict__ d){
  double a[9];
#pragma unroll
  for(int i=0;i<9;i++) a[i]=0.0;
  for(int n=blockIdx.x*blockDim.x+threadIdx.x;n<NN;n+=gridDim.x*blockDim.x){
    double x=d[n*FIN],y=d[n*FIN+1],z=d[n*FIN+2];
    a[0]+=x;a[1]+=y;a[2]+=z;a[3]+=x*x;a[4]+=x*y;a[5]+=x*z;a[6]+=y*y;a[7]+=y*z;a[8]+=z*z;
  }
  __shared__ double sm[256];
  for(int c=0;c<9;c++){
    sm[threadIdx.x]=a[c];__syncthreads();
    for(int o=128;o;o>>=1){ if(threadIdx.x<(unsigned)o) sm[threadIdx.x]+=sm[threadIdx.x+o]; __syncthreads(); }
    if(!threadIdx.x) g_pp[blockIdx.x*9+c]=sm[0];
    __syncthreads();
  }
}

__global__ void kpos_final(){
  __shared__ double sm[512];
  __shared__ double tot[9];
  int t=threadIdx.x;
  for(int c=0;c<9;c++){
    sm[t]=g_pp[t*9+c];__syncthreads();
    for(int o=256;o;o>>=1){ if(t<o) sm[t]+=sm[t+o]; __syncthreads(); }
    if(!t) tot[c]=sm[0];
    __syncthreads();
  }
  if(t<OD) g_pool[t]=0.0;
  if(!t){
    double Nn=(double)NN;
    double mx=tot[0]/Nn,my=tot[1]/Nn,mz=tot[2]/Nn;
    g_mu[0]=mx;g_mu[1]=my;g_mu[2]=mz;
    g_cov[0]=tot[3]-Nn*mx*mx; g_cov[1]=tot[4]-Nn*mx*my; g_cov[2]=tot[5]-Nn*mx*mz;
    g_cov[3]=tot[6]-Nn*my*my; g_cov[4]=tot[7]-Nn*my*mz; g_cov[5]=tot[8]-Nn*mz*mz;
    g_maxbits=0u;
  }
}

__global__ void kmaxabs(const float* __restrict__ d){
  float m=0.f;
  float m0=(float)g_mu[0],m1=(float)g_mu[1],m2=(float)g_mu[2];
  for(int n=blockIdx.x*blockDim.x+threadIdx.x;n<NN;n+=gridDim.x*blockDim.x){
    m=fmaxf(m,fabsf(d[n*FIN]-m0));
    m=fmaxf(m,fabsf(d[n*FIN+1]-m1));
    m=fmaxf(m,fabsf(d[n*FIN+2]-m2));
  }
  __shared__ float sm[256];
  sm[threadIdx.x]=m;__syncthreads();
  for(int o=128;o;o>>=1){ if(threadIdx.x<(unsigned)o) sm[threadIdx.x]=fmaxf(sm[threadIdx.x],sm[threadIdx.x+o]); __syncthreads(); }
  if(!threadIdx.x) atomicMax(&g_maxbits,__float_as_uint(sm[0]));
}

// ---------- analytic 3x3 symmetric eigh (ascending) ----------
__global__ void keig(){
  double a00=g_cov[0],a01=g_cov[1],a02=g_cov[2],a11=g_cov[3],a12=g_cov[4],a22=g_cov[5];
  double V[3][3], lam[3];
  double p1=a01*a01+a02*a02+a12*a12;
  if(p1==0.0){
    double dd[3]={a00,a11,a22}; int idx[3]={0,1,2};
    for(int i=0;i<2;i++)for(int j=0;j<2-i;j++)
      if(dd[j]>dd[j+1]){double tt=dd[j];dd[j]=dd[j+1];dd[j+1]=tt;int ti=idx[j];idx[j]=idx[j+1];idx[j+1]=ti;}
    for(int k=0;k<3;k++){lam[k]=dd[k];for(int j=0;j<3;j++)V[j][k]=(j==idx[k])?1.0:0.0;}
  }else{
    double q=(a00+a11+a22)/3.0;
    double b00=a00-q,b11=a11-q,b22=a22-q;
    double p2=b00*b00+b11*b11+b22*b22+2.0*p1;
    double p=sqrt(p2/6.0);
    double c00=b00/p,c01=a01/p,c02=a02/p,c11=b11/p,c12=a12/p,c22=b22/p;
    double detB=c00*(c11*c22-c12*c12)-c01*(c01*c22-c12*c02)+c02*(c01*c12-c11*c02);
    double r=detB*0.5; r=r<-1.0?-1.0:(r>1.0?1.0:r);
    double phi=acos(r)/3.0;
    const double tp3=2.0943951023931953;
    lam[2]=q+2.0*p*cos(phi);
    lam[0]=q+2.0*p*cos(phi+tp3);
    lam[1]=3.0*q-lam[0]-lam[2];
    for(int kk=0;kk<2;kk++){
      int k=(kk==0)?0:2;
      double l=lam[k];
      double r0x=a00-l,r0y=a01,r0z=a02;
      double r1x=a01,r1y=a11-l,r1z=a12;
      double r2x=a02,r2y=a12,r2z=a22-l;
      double cx[3],cy[3],cz[3];
      cx[0]=r0y*r1z-r0z*r1y; cy[0]=r0z*r1x-r0x*r1z; cz[0]=r0x*r1y-r0y*r1x;
      cx[1]=r0y*r2z-r0z*r2y; cy[1]=r0z*r2x-r0x*r2z; cz[1]=r0x*r2y-r0y*r2x;
      cx[2]=r1y*r2z-r1z*r2y; cy[2]=r1z*r2x-r1x*r2z; cz[2]=r1x*r2y-r1y*r2x;
      int best=0; double bn=-1.0;
      for(int i=0;i<3;i++){double nn=cx[i]*cx[i]+cy[i]*cy[i]+cz[i]*cz[i];if(nn>bn){bn=nn;best=i;}}
      double innorm=1.0/sqrt(bn);
      V[0][k]=cx[best]*innorm;V[1][k]=cy[best]*innorm;V[2][k]=cz[best]*innorm;
    }
    double mx=V[1][2]*V[2][0]-V[2][2]*V[1][0];
    double my=V[2][2]*V[0][0]-V[0][2]*V[2][0];
    double mz=V[0][2]*V[1][0]-V[1][2]*V[0][0];
    double innm=1.0/sqrt(mx*mx+my*my+mz*mz);
    V[0][1]=mx*innm;V[1][1]=my*innm;V[2][1]=mz*innm;
  }
  for(int k=0;k<3;k++){
    int bj=0; double bv=fabs(V[0][k]);
    for(int j=1;j<3;j++){double av=fabs(V[j][k]);if(av>bv){bv=av;bj=j;}}
    double sgn=(V[bj][k]<0.0)?-1.0:1.0;
    if((FLIP_MASK>>k)&1) sgn=-sgn;
    V[0][k]*=sgn;V[1][k]*=sgn;V[2][k]*=sgn;
  }
  float mab=__uint_as_float(g_maxbits);
  float s=(1.0f/mab)*0.999999f;
  for(int j=0;j<3;j++)for(int k=0;k<3;k++) g_M[j*3+k]=(float)V[j][k]*s;
}

// ---------- feature LN stats ----------
__global__ void kfeat_partials(const float* __restrict__ d){
  double s=0.0,sq=0.0;
  for(int idx=blockIdx.x*blockDim.x+threadIdx.x;idx<NN*OD;idx+=gridDim.x*blockDim.x){
    int n=idx>>5,c=idx&31;
    double v=d[n*FIN+3+c];
    s+=v;sq+=v*v;
  }
  __shared__ double s1[256],s2[256];
  int t=threadIdx.x;
  s1[t]=s;s2[t]=sq;__syncthreads();
  for(int o=128;o;o>>=1){ if(t<o){s1[t]+=s1[t+o];s2[t]+=s2[t+o];} __syncthreads(); }
  if(!t){g_fp[blockIdx.x*2]=s1[0];g_fp[blockIdx.x*2+1]=s2[0];}
}

__global__ void kfeat_final(){
  __shared__ double s1[512],s2[512];
  int t=threadIdx.x;
  s1[t]=g_fp[t*2];s2[t]=g_fp[t*2+1];__syncthreads();
  for(int o=256;o;o>>=1){ if(t<o){s1[t]+=s1[t+o];s2[t]+=s2[t+o];} __syncthreads(); }
  if(!t){
    double M=(double)NN*OD;
    double mu=s1[0]/M;
    double var=s2[0]/M-mu*mu;
    g_fmean=(float)mu;
    g_fstd=(float)sqrt(var>0.0?var:0.0);
  }
}

// ---------- build layer-0 features ----------
__global__ void kbuildX(const float* __restrict__ d,const float* __restrict__ w,const float* __restrict__ b){
  int n=blockIdx.x*blockDim.x+threadIdx.x;
  if(n>=NN)return;
  float p0=d[n*FIN]-(float)g_mu[0];
  float p1=d[n*FIN+1]-(float)g_mu[1];
  float p2=d[n*FIN+2]-(float)g_mu[2];
#pragma unroll
  for(int k=0;k<3;k++)
    g_X0[n*FIN+k]=p0*g_M[k]+p1*g_M[3+k]+p2*g_M[6+k];
  float fm=g_fmean, inv=1.f/(g_fstd+1e-5f);
#pragma unroll
  for(int c=0;c<OD;c++)
    g_X0[n*FIN+3+c]=(d[n*FIN+3+c]-fm)*inv*w[c]+b[c];
}

// ---------- counting sort by dst ----------
__global__ void khz(){
  int i=blockIdx.x*blockDim.x+threadIdx.x;
  if(i<NN) g_hist[i]=0;
}
__global__ void khist(const int* __restrict__ dst){
  for(int e=blockIdx.x*blockDim.x+threadIdx.x;e<NE;e+=gridDim.x*blockDim.x)
    atomicAdd(&g_hist[dst[e]],1);
}
__global__ void kscanA(){
  __shared__ int s[1024];
  int t=threadIdx.x;
  int i=blockIdx.x*1024+t;
  s[t]=(i<NN)?g_hist[i]:0;
  __syncthreads();
  for(int o=1;o<1024;o<<=1){
    int tv=(t>=o)?s[t-o]:0;
    __syncthreads();
    s[t]+=tv;
    __syncthreads();
  }
  if(i<NN) g_inc[i]=s[t];
  if(t==1023) g_btot[blockIdx.x]=s[1023];
}
__global__ void kscanB(){
  int nb=(NN+1023)/1024, run=0;
  for(int b=0;b<nb;b++){g_boff[b]=run;run+=g_btot[b];}
  g_rowptr[NN]=run;
}
__global__ void kscanC(){
  int i=blockIdx.x*blockDim.x+threadIdx.x;
  if(i<NN){
    int rp=g_boff[i>>10]+g_inc[i]-g_hist[i];
    g_rowptr[i]=rp;
    g_cursor[i]=rp;
  }
}
__global__ void kscatter(const int* __restrict__ src,const int* __restrict__ dst,const int* __restrict__ et){
  for(int e=blockIdx.x*blockDim.x+threadIdx.x;e<NE;e+=gridDim.x*blockDim.x){
    int d=dst[e];
    int p=atomicAdd(&g_cursor[d],1);
    g_se[p]=src[e]|(et[e]<<17);
  }
}

// ---------- per-relation transform via tf32 mma.sync (m16n8k8) ----------
// Block: 256 threads = 8 warps; 128 nodes x 32 ch for relation blockIdx.y.
// Warp computes 16 nodes: A frags from smem X tile, B frags from smem W.
__global__ void ktrans_mma(int useX0,int Fin,int K,const float* __restrict__ W,
                           const float* __restrict__ qv,const float* __restrict__ kv){
  __shared__ unsigned sW[40*32];      // [k][c], tf32 bits, zero-padded to K
  __shared__ unsigned sX[128*41];     // [nl][k], stride K+1, tf32 bits
  int r=blockIdx.y, nb=blockIdx.x*128;
  int t=threadIdx.x;
  int SXS=K+1;
  const float* Wr=W+(size_t)r*Fin*OD;
  for(int i=t;i<K*OD;i+=256){
    int k=i>>5;
    float v=(k<Fin)?Wr[i]:0.f;
    sW[i]=tf32cvt(v);
  }
  const float* X=useX0?g_X0:g_Xc;
  for(int i=t;i<128*K;i+=256){
    int nl=i/K, f=i-nl*K;
    int n=nb+nl;
    float v=(n<NN&&f<Fin)?X[(size_t)n*Fin+f]:0.f;
    sX[nl*SXS+f]=tf32cvt(v);
  }
  __syncthreads();
  int w=t>>5, lane=t&31;
  int mrow=w*16;
  int quad=lane>>2, qt=lane&3;
  float c[4][4];
#pragma unroll
  for(int i=0;i<4;i++)
#pragma unroll
    for(int j=0;j<4;j++) c[i][j]=0.f;
  int nk=K>>3;
  for(int kb=0;kb<nk;kb++){
    int k0=kb*8;
    unsigned a0=sX[(mrow+quad  )*SXS+k0+qt  ];
    unsigned a1=sX[(mrow+quad+8)*SXS+k0+qt  ];
    unsigned a2=sX[(mrow+quad  )*SXS+k0+qt+4];
    unsigned a3=sX[(mrow+quad+8)*SXS+k0+qt+4];
#pragma unroll
    for(int nt=0;nt<4;nt++){
      unsigned b0=sW[(k0+qt  )*OD+nt*8+quad];
      unsigned b1=sW[(k0+qt+4)*OD+nt*8+quad];
      asm volatile("mma.sync.aligned.m16n8k8.row.col.f32.tf32.tf32.f32 "
        "{%0,%1,%2,%3},{%4,%5,%6,%7},{%8,%9},{%0,%1,%2,%3};"
        : "+f"(c[nt][0]),"+f"(c[nt][1]),"+f"(c[nt][2]),"+f"(c[nt][3])
        : "r"(a0),"r"(a1),"r"(a2),"r"(a3),"r"(b0),"r"(b1));
    }
  }
  int nlo=nb+mrow+quad, nhi=nlo+8;
  bool oklo=(nlo<NN), okhi=(nhi<NN);
  float qlo=0.f,klo=0.f,qhi=0.f,khi=0.f;
#pragma unroll
  for(int nt=0;nt<4;nt++){
    int col=nt*8+qt*2;
    float q0=qv[col],q1=qv[col+1],k0v=kv[col],k1v=kv[col+1];
    qlo+=c[nt][0]*q0+c[nt][1]*q1; klo+=c[nt][0]*k0v+c[nt][1]*k1v;
    qhi+=c[nt][2]*q0+c[nt][3]*q1; khi+=c[nt][2]*k0v+c[nt][3]*k1v;
    if(oklo){ float2 s2; s2.x=c[nt][0]; s2.y=c[nt][1];
      *(float2*)&g_xr[((size_t)r*NN+nlo)*OD+col]=s2; }
    if(okhi){ float2 s2; s2.x=c[nt][2]; s2.y=c[nt][3];
      *(float2*)&g_xr[((size_t)r*NN+nhi)*OD+col]=s2; }
  }
#pragma unroll
  for(int o=1;o<4;o<<=1){
    qlo+=__shfl_xor_sync(0xffffffffu,qlo,o); klo+=__shfl_xor_sync(0xffffffffu,klo,o);
    qhi+=__shfl_xor_sync(0xffffffffu,qhi,o); khi+=__shfl_xor_sync(0xffffffffu,khi,o);
  }
  if(qt==0){
    if(oklo){ g_qd[r*NN+nlo]=qlo; g_kd[r*NN+nlo]=klo; }
    if(okhi){ g_qd[r*NN+nhi]=qhi; g_kd[r*NN+nhi]=khi; }
  }
}

// ---------- attention + aggregation: warp per destination node ----------
__global__ void kagg(const float* __restrict__ bias,int useprev){
  int lane=threadIdx.x&31;
  int warp=(blockIdx.x*blockDim.x+threadIdx.x)>>5;
  int nwarps=(gridDim.x*blockDim.x)>>5;
  float bv=bias[lane];
  float tsum=0.f,tsq=0.f;
  for(int n=warp;n<NN;n+=nwarps){
    int s0=g_rowptr[n], deg=g_rowptr[n+1]-s0;
    float hv;
    if(deg<=128){
      int addr_r[4]; float e_r[4];
      float m=-3.0e38f;
#pragma unroll
      for(int tt=0;tt<4;tt++){
        int i=lane+tt*32;
        e_r[tt]=-3.0e38f; addr_r[tt]=0;
        if(i<deg){
          int se=g_se[s0+i];
          int sv=se&0x1FFFF, et=se>>17;
          addr_r[tt]=(et*NN+sv)*OD;
          float a=g_qd[et*NN+n]+g_kd[et*NN+sv];
          a=a>0.f?a:0.2f*a;
          e_r[tt]=a;
          m=fmaxf(m,a);
        }
      }
      for(int o=16;o;o>>=1) m=fmaxf(m,__shfl_xor_sync(0xffffffffu,m,o));
      float den=0.f;
#pragma unroll
      for(int tt=0;tt<4;tt++){
        int i=lane+tt*32;
        if(i<deg){ e_r[tt]=__expf(e_r[tt]-m); den+=e_r[tt]; }
      }
      for(int o=16;o;o>>=1) den+=__shfl_xor_sync(0xffffffffu,den,o);
      float inv=1.f/(den+1e-16f);
      float acc=0.f;
#pragma unroll
      for(int tt=0;tt<4;tt++){
        int base=tt*32;
        if(base<deg){
          int cnt=deg-base; if(cnt>32) cnt=32;
          for(int l=0;l<cnt;l++){
            float e=__shfl_sync(0xffffffffu,e_r[tt],l);
            int ad=__shfl_sync(0xffffffffu,addr_r[tt],l);
            acc+=e*g_xr[ad+lane];
          }
        }
      }
      hv=acc*inv+bv;
    } else {
      float m=-3.0e38f;
      for(int i=lane;i<deg;i+=32){
        int idx=s0+i;
        int se=g_se[idx];
        int sv=se&0x1FFFF, et=se>>17;
        float a=g_qd[et*NN+n]+g_kd[et*NN+sv];
        a=a>0.f?a:0.2f*a;
        g_alpha[idx]=a;
        m=fmaxf(m,a);
      }
      for(int o=16;o;o>>=1) m=fmaxf(m,__shfl_xor_sync(0xffffffffu,m,o));
      float den=0.f;
      for(int i=lane;i<deg;i+=32){
        int idx=s0+i;
        float e=__expf(g_alpha[idx]-m);
        g_alpha[idx]=e;
        den+=e;
      }
      for(int o=16;o;o>>=1) den+=__shfl_xor_sync(0xffffffffu,den,o);
      __syncwarp();
      float inv=1.f/(den+1e-16f);
      float acc=0.f;
      for(int j=0;j<deg;j++){
        int idx=s0+j;
        float e=g_alpha[idx];
        int se=g_se[idx];
        int sv=se&0x1FFFF, et=se>>17;
        acc+=e*g_xr[((size_t)et*NN+sv)*OD+lane];
      }
      hv=acc*inv+bv;
    }
    if(useprev) hv+=g_Xc[n*OD+lane];
    g_h[n*OD+lane]=hv;
    tsum+=hv; tsq+=hv*hv;
  }
  __shared__ double d1[256],d2[256];
  int t=threadIdx.x;
  d1[t]=(double)tsum; d2[t]=(double)tsq;
  __syncthreads();
  for(int o=128;o;o>>=1){ if(t<o){d1[t]+=d1[t+o];d2[t]+=d2[t+o];} __syncthreads(); }
  if(!t){g_hp[blockIdx.x*2]=d1[0];g_hp[blockIdx.x*2+1]=d2[0];}
}

__global__ void krstats(){
  __shared__ double sa[1024],sb[1024];
  int t=threadIdx.x;
  sa[t]=g_hp[t*2]; sb[t]=g_hp[t*2+1];
  __syncthreads();
  for(int o=512;o;o>>=1){ if(t<o){sa[t]+=sa[t+o];sb[t]+=sb[t+o];} __syncthreads(); }
  if(!t){
    double M=(double)NN*OD;
    double mu=sa[0]/M;
    double var=sb[0]/M-mu*mu;
    g_hmu=(float)mu;
    g_hsig=(float)sqrt(var>0?var:0);
  }
}

__global__ void knorm(const float* __restrict__ w,const float* __restrict__ b){
  int idx=blockIdx.x*blockDim.x+threadIdx.x;
  if(idx>=NN*OD)return;
  int c=idx&31;
  float v=(g_h[idx]-g_hmu)/(g_hsig+1e-5f)*w[c]+b[c];
  g_Xc[idx]=v/(1.f+__expf(-v));
}

__global__ void kpoolp(){
  int lane=threadIdx.x&31;
  int warp=(blockIdx.x*blockDim.x+threadIdx.x)>>5;
  int nw=(gridDim.x*blockDim.x)>>5;
  double s=0.0;
  for(int n=warp;n<NN;n+=nw) s+=(double)g_Xc[n*OD+lane];
  atomicAdd(&g_pool[lane],s);
}

__global__ void kout(const float* __restrict__ Wl,const float* __restrict__ bl,float* __restrict__ out){
  int j=threadIdx.x;
  float s=bl[j];
  for(int c=0;c<OD;c++) s+=(float)(g_pool[c]/(double)NN)*Wl[j*OD+c];
  out[j]=s/(1.f+expf(-s));
}

extern "C" void kernel_launch(void* const* d_in,const int* in_sizes,int n_in,
                              void* d_out,int out_size){
  (void)in_sizes;(void)n_in;(void)out_size;
  const float* X1 =(const float*)d_in[0];
  const int*   ei =(const int*)  d_in[2];
  const int*   et =(const int*)  d_in[3];
  const float* W0 =(const float*)d_in[6];
  const float* q0 =(const float*)d_in[7];
  const float* k0 =(const float*)d_in[8];
  const float* b0 =(const float*)d_in[9];
  const float* Ws =(const float*)d_in[10];
  const float* qs =(const float*)d_in[11];
  const float* ks =(const float*)d_in[12];
  const float* bs =(const float*)d_in[13];
  const float* lnw=(const float*)d_in[14];
  const float* lnb=(const float*)d_in[15];
  const float* l1w=(const float*)d_in[16];
  const float* l1b_=(const float*)d_in[17];
  const float* lW =(const float*)d_in[18];
  const float* lb =(const float*)d_in[19];
  float* out=(float*)d_out;
  const int* src=ei;
  const int* dst=ei+NE;

  kpos_partials<<<SB,256>>>(X1);
  kpos_final<<<1,512>>>();
  kmaxabs<<<SB,256>>>(X1);
  keig<<<1,1>>>();
  kfeat_partials<<<SB,256>>>(X1);
  kfeat_final<<<1,512>>>();
  kbuildX<<<(NN+255)/256,256>>>(X1,l1w,l1b_);

  khz<<<(NN+255)/256,256>>>();
  khist<<<2048,256>>>(dst);
  kscanA<<<(NN+1023)/1024,1024>>>();
  kscanB<<<1,1>>>();
  kscanC<<<(NN+255)/256,256>>>();
  kscatter<<<2048,256>>>(src,dst,et);

  for(int i=0;i<4;i++){
    int useX0=(i==0);
    int Fin=useX0?FIN:OD;
    int K=useX0?40:32;
    const float* W =useX0?W0:(Ws+(size_t)(i-1)*NR*OD*OD);
    const float* qv=useX0?q0:(qs+(i-1)*OD);
    const float* kv=useX0?k0:(ks+(i-1)*OD);
    const float* bv=useX0?b0:(bs+(i-1)*OD);
    ktrans_mma<<<dim3((NN+127)/128,NR),256>>>(useX0,Fin,K,W,qv,kv);
    kagg<<<GA,256>>>(bv,i>0);
    krstats<<<1,1024>>>();
    knorm<<<(NN*OD+255)/256,256>>>(lnw+i*OD,lnb+i*OD);
  }

  kpoolp<<<512,256>>>();
  kout<<<1,256>>>(lW,lb,out);
}